// round 14
// baseline (speedup 1.0000x reference)
#include <cuda_runtime.h>
#include <cuda_bf16.h>
#include <math.h>

#define NM      4096
#define NPTS    131072
#define GRES    16

typedef unsigned int u32;

// ---- scratch (no allocations allowed) ----
__device__ int g_cnt[NM];      // zero at load; re-zeroed by k_mlp each call
__device__ int g_start[NM];
__device__ int g_vox[NPTS];    // packed: voxel | (rank<<12)
__device__ int g_sorted[NPTS];

__global__ void k_index(const float* __restrict__ pts) {
    int n = blockIdx.x * blockDim.x + threadIdx.x;
    if (n >= NPTS) return;
    float x = pts[3 * n + 0], y = pts[3 * n + 1], z = pts[3 * n + 2];
    int ix = (int)fminf(fmaxf(x * (float)GRES, 0.f), (float)(GRES - 1));
    int iy = (int)fminf(fmaxf(y * (float)GRES, 0.f), (float)(GRES - 1));
    int iz = (int)fminf(fmaxf(z * (float)GRES, 0.f), (float)(GRES - 1));
    int v = ix * (GRES * GRES) + iy * GRES + iz;
    int r = atomicAdd(&g_cnt[v], 1);
    g_vox[n] = v | (r << 12);
}

__global__ void k_scan() {
    __shared__ int sh[1024];
    int t = threadIdx.x;
    int c0 = g_cnt[4 * t + 0], c1 = g_cnt[4 * t + 1];
    int c2 = g_cnt[4 * t + 2], c3 = g_cnt[4 * t + 3];
    int s = c0 + c1 + c2 + c3;
    sh[t] = s;
    __syncthreads();
    for (int d = 1; d < 1024; d <<= 1) {
        int v = (t >= d) ? sh[t - d] : 0;
        __syncthreads();
        sh[t] += v;
        __syncthreads();
    }
    int excl = sh[t] - s;
    g_start[4 * t + 0] = excl; excl += c0;
    g_start[4 * t + 1] = excl; excl += c1;
    g_start[4 * t + 2] = excl; excl += c2;
    g_start[4 * t + 3] = excl;
}

__global__ void k_scatter() {
    int n = blockIdx.x * blockDim.x + threadIdx.x;
    if (n >= NPTS) return;
    int pv = g_vox[n];
    g_sorted[g_start[pv & 4095] + (pv >> 12)] = n;
}

// ---- bf16 split helpers ----
__device__ __forceinline__ u32 pack_split(float f) {
    __nv_bfloat16 h1 = __float2bfloat16(f);
    float f1 = __bfloat162float(h1);
    __nv_bfloat16 h2 = __float2bfloat16(f - f1);
    return (u32)__bfloat16_as_ushort(h1) | ((u32)__bfloat16_as_ushort(h2) << 16);
}
// (bf16(v), bf16(v)) packed
__device__ __forceinline__ u32 dup2(float v) {
    u32 r;
    asm("cvt.rn.bf16x2.f32 %0, %1, %1;" : "=r"(r) : "f"(v));
    return r;
}
// (0, bf16(v - f32(bf16(v)))) : residual in low half
__device__ __forceinline__ u32 res2(float v, u32 d) {
    float f1 = __uint_as_float(d << 16);
    float x2 = v - f1;
    u32 r;
    asm("cvt.rn.bf16x2.f32 %0, %1, %1;" : "=r"(r) : "f"(x2));
    return r & 0xFFFFu;
}

// mma.sync m16n8k16 row.col f32 += bf16*bf16
__device__ __forceinline__ void mma4(float* C, const u32* a, u32 b0, u32 b1) {
    asm volatile(
        "mma.sync.aligned.m16n8k16.row.col.f32.bf16.bf16.f32 "
        "{%0,%1,%2,%3}, {%4,%5,%6,%7}, {%8,%9}, {%0,%1,%2,%3};"
        : "+f"(C[0]), "+f"(C[1]), "+f"(C[2]), "+f"(C[3])
        : "r"(a[0]), "r"(a[1]), "r"(a[2]), "r"(a[3]), "r"(b0), "r"(b1));
}

// A-frag build: v0=(row g,c0) v1=(row g,c1) v2=(row g+8,c0) v3=(row g+8,c1)
__device__ __forceinline__ void build_afrag(float v0, float v1, float v2, float v3,
                                            u32* P1, u32* P2) {
    P1[0] = dup2(v0); P1[1] = dup2(v2); P1[2] = dup2(v1); P1[3] = dup2(v3);
    P2[0] = res2(v0, P1[0]); P2[1] = res2(v2, P1[1]);
    P2[2] = res2(v1, P1[2]); P2[3] = res2(v3, P1[3]);
}

// ---- weight staging with input-slot permutation ----
// slot d (position in K) holds real input neuron rd = blk*8 + (dl<4 ? 2dl : 2(dl-4)+1)
// so that chained C fragments line up with A slots with zero data movement.
template<int DREAL, int DPAD>
__device__ __forceinline__ void stage_wf(const float* __restrict__ gsrc,
                                         u32* Wf, int tileOff, int tid) {
    const int total = 32 * DPAD;
    for (int i = tid; i < total; i += 64) {
        int no = i / DPAD;
        int d  = i % DPAD;
        int blk = d >> 3, dl = d & 7;
        int rd = blk * 8 + ((dl < 4) ? (2 * dl) : (2 * (dl - 4) + 1));
        float w = (rd < DREAL) ? gsrc[no * DREAL + rd] : 0.f;
        u32 pk = pack_split(w);
        int rg = dl >> 2;
        int tcb = dl & 3;
        int lane = ((no & 7) << 2) | tcb;
        int nt = no >> 3;
        Wf[(((tileOff + blk * 4 + nt) << 5) + lane) * 2 + rg] = pk;
    }
}

// embedding column value. c: 0..2 raw coord; 3.. -> sin/cos(2^k p); >=cmax -> 0
__device__ __forceinline__ float embcol(float x, float y, float z, int c, int cmax) {
    int u = c - 3;
    int k = u / 6;
    int comp = u - 6 * k;
    int c3 = (comp < 3) ? comp : comp - 3;
    float p = (c3 == 0) ? x : ((c3 == 1) ? y : z);
    float a = p * __uint_as_float((u32)(127 + k) << 23);
    float sv = __sinf(a), cv = __cosf(a);
    float tv = (comp < 3) ? sv : cv;
    float raw = (c == 0) ? x : ((c == 1) ? y : z);
    float r = (c < 3) ? raw : tv;
    return (c < cmax) ? r : 0.f;
}

// smem layout (u32): Wf[6144] | small[264 floats]
#define OFF_SM  6144
#define SP_TOT  6408
// small floats: sw[0:32) b0[32:64) b1[64:96) fb[96:128) vb[128:160)
//               rT[160:256) rb[256:259) sb[259]

__global__ void __launch_bounds__(64, 6) k_mlp(
    const float* __restrict__ pts, const float* __restrict__ vdirs,
    const float* __restrict__ w0, const float* __restrict__ b0,
    const float* __restrict__ w1, const float* __restrict__ b1,
    const float* __restrict__ fw, const float* __restrict__ fb,
    const float* __restrict__ sw, const float* __restrict__ sb,
    const float* __restrict__ vw, const float* __restrict__ vb,
    const float* __restrict__ rw, const float* __restrict__ rb,
    float* __restrict__ out)
{
    const int vox = blockIdx.x;
    const int tid = threadIdx.x;

    __shared__ __align__(16) u32 spool[SP_TOT];
    u32* Wf = spool;
    float* sm = (float*)(spool + OFF_SM);

    const int start = g_start[vox];
    const int count = g_cnt[vox];

    // stage weights: tile offsets (in 64-u32 tiles): w0:0(32) w1:32(16) fw:48(16) vw:64(32)
    stage_wf<63, 64>(w0 + (size_t)vox * 2016, Wf, 0,  tid);
    stage_wf<32, 32>(w1 + (size_t)vox * 1024, Wf, 32, tid);
    stage_wf<32, 32>(fw + (size_t)vox * 1024, Wf, 48, tid);
    stage_wf<59, 64>(vw + (size_t)vox * 1888, Wf, 64, tid);

    for (int i = tid; i < 96; i += 64) {
        int c = i >> 5, d = i & 31;
        sm[160 + d * 3 + c] = rw[(size_t)vox * 96 + i];
    }
    if (tid < 32) {
        sm[tid]       = sw[(size_t)vox * 32 + tid];
        sm[32 + tid]  = b0[(size_t)vox * 32 + tid];
        sm[64 + tid]  = b1[(size_t)vox * 32 + tid];
        sm[96 + tid]  = fb[(size_t)vox * 32 + tid];
        sm[128 + tid] = vb[(size_t)vox * 32 + tid];
    }
    if (tid < 3) sm[256 + tid] = rb[(size_t)vox * 3 + tid];
    if (tid == 0) {
        sm[259] = sb[vox];
        g_cnt[vox] = 0;   // reset for next replay
    }
    __syncthreads();

    const int warp = tid >> 5, lane = tid & 31;
    const int g = lane >> 2, tc = lane & 3;
    const unsigned FULL = 0xFFFFFFFFu;

    for (int base = warp * 32; base < count; base += 64) {
        const int i = base + lane;
        const bool act = (i < count);
        int n = 0;
        float px = 0.f, py = 0.f, pz = 0.f, dvx = 0.f, dvy = 0.f, dvz = 0.f;
        if (act) {
            n = g_sorted[start + i];
            px = pts[3 * n + 0]; py = pts[3 * n + 1]; pz = pts[3 * n + 2];
            int ray = n >> 7;
            dvx = vdirs[3 * ray + 0]; dvy = vdirs[3 * ray + 1]; dvz = vdirs[3 * ray + 2];
        }

        // gather the 4 rows this thread contributes to: j -> row 16*(j>>1)+8*(j&1)+g
        float qx[4], qy[4], qz[4], ex[4], ey[4], ez[4];
#pragma unroll
        for (int j = 0; j < 4; j++) {
            int src = 16 * (j >> 1) + 8 * (j & 1) + g;
            qx[j] = __shfl_sync(FULL, px, src);
            qy[j] = __shfl_sync(FULL, py, src);
            qz[j] = __shfl_sync(FULL, pz, src);
            ex[j] = __shfl_sync(FULL, dvx, src);
            ey[j] = __shfl_sync(FULL, dvy, src);
            ez[j] = __shfl_sync(FULL, dvz, src);
        }

        float Ca[2][4][4], Cb[2][4][4];
        u32 A1[2][4], A2[2][4];

        // ---- layer0: 63 -> 32 (tiles 0..31), A from xyz embedding ----
#pragma unroll
        for (int nt = 0; nt < 4; nt++) {
            float bb0 = sm[32 + nt * 8 + 2 * tc], bb1 = sm[32 + nt * 8 + 2 * tc + 1];
#pragma unroll
            for (int mt = 0; mt < 2; mt++) {
                Ca[mt][nt][0] = bb0; Ca[mt][nt][1] = bb1;
                Ca[mt][nt][2] = bb0; Ca[mt][nt][3] = bb1;
            }
        }
#pragma unroll
        for (int kt = 0; kt < 8; kt++) {
            int c0 = 8 * kt + 2 * tc, c1 = c0 + 1;
#pragma unroll
            for (int mt = 0; mt < 2; mt++) {
                float v0 = embcol(qx[2 * mt], qy[2 * mt], qz[2 * mt], c0, 63);
                float v1 = embcol(qx[2 * mt], qy[2 * mt], qz[2 * mt], c1, 63);
                float v2 = embcol(qx[2 * mt + 1], qy[2 * mt + 1], qz[2 * mt + 1], c0, 63);
                float v3 = embcol(qx[2 * mt + 1], qy[2 * mt + 1], qz[2 * mt + 1], c1, 63);
                build_afrag(v0, v1, v2, v3, A1[mt], A2[mt]);
            }
#pragma unroll
            for (int nt = 0; nt < 4; nt++) {
                const u32* wr = Wf + ((0 + kt * 4 + nt) << 6) + lane * 2;
                u32 wb0 = wr[0], wb1 = wr[1];
                mma4(Ca[0][nt], A1[0], wb0, wb1);
                mma4(Ca[0][nt], A2[0], wb0, wb1);
                mma4(Ca[1][nt], A1[1], wb0, wb1);
                mma4(Ca[1][nt], A2[1], wb0, wb1);
            }
        }
#pragma unroll
        for (int mt = 0; mt < 2; mt++)
#pragma unroll
            for (int nt = 0; nt < 4; nt++)
#pragma unroll
                for (int r = 0; r < 4; r++)
                    Ca[mt][nt][r] = fmaxf(Ca[mt][nt][r], 0.f);

        // ---- layer1: 32 -> 32 (tiles 32..47), chained from Ca ----
#pragma unroll
        for (int nt = 0; nt < 4; nt++) {
            float bb0 = sm[64 + nt * 8 + 2 * tc], bb1 = sm[64 + nt * 8 + 2 * tc + 1];
#pragma unroll
            for (int mt = 0; mt < 2; mt++) {
                Cb[mt][nt][0] = bb0; Cb[mt][nt][1] = bb1;
                Cb[mt][nt][2] = bb0; Cb[mt][nt][3] = bb1;
            }
        }
#pragma unroll
        for (int kt = 0; kt < 4; kt++) {
#pragma unroll
            for (int mt = 0; mt < 2; mt++)
                build_afrag(Ca[mt][kt][0], Ca[mt][kt][1], Ca[mt][kt][2], Ca[mt][kt][3],
                            A1[mt], A2[mt]);
#pragma unroll
            for (int nt = 0; nt < 4; nt++) {
                const u32* wr = Wf + ((32 + kt * 4 + nt) << 6) + lane * 2;
                u32 wb0 = wr[0], wb1 = wr[1];
                mma4(Cb[0][nt], A1[0], wb0, wb1);
                mma4(Cb[0][nt], A2[0], wb0, wb1);
                mma4(Cb[1][nt], A1[1], wb0, wb1);
                mma4(Cb[1][nt], A2[1], wb0, wb1);
            }
        }
#pragma unroll
        for (int mt = 0; mt < 2; mt++)
#pragma unroll
            for (int nt = 0; nt < 4; nt++)
#pragma unroll
                for (int r = 0; r < 4; r++)
                    Cb[mt][nt][r] = fmaxf(Cb[mt][nt][r], 0.f);

        // ---- sigma partials from h = Cb (natural neuron cols) ----
        float sg[4] = {0.f, 0.f, 0.f, 0.f};
#pragma unroll
        for (int mt = 0; mt < 2; mt++)
#pragma unroll
            for (int h = 0; h < 2; h++) {
                float s = 0.f;
#pragma unroll
                for (int nt = 0; nt < 4; nt++) {
                    s += Cb[mt][nt][2 * h]     * sm[nt * 8 + 2 * tc];
                    s += Cb[mt][nt][2 * h + 1] * sm[nt * 8 + 2 * tc + 1];
                }
                sg[2 * mt + h] = s;
            }

        // ---- feat: 32 -> 32 (tiles 48..63), chained from Cb, NO relu ----
#pragma unroll
        for (int nt = 0; nt < 4; nt++) {
            float bb0 = sm[96 + nt * 8 + 2 * tc], bb1 = sm[96 + nt * 8 + 2 * tc + 1];
#pragma unroll
            for (int mt = 0; mt < 2; mt++) {
                Ca[mt][nt][0] = bb0; Ca[mt][nt][1] = bb1;
                Ca[mt][nt][2] = bb0; Ca[mt][nt][3] = bb1;
            }
        }
#pragma unroll
        for (int kt = 0; kt < 4; kt++) {
#pragma unroll
            for (int mt = 0; mt < 2; mt++)
                build_afrag(Cb[mt][kt][0], Cb[mt][kt][1], Cb[mt][kt][2], Cb[mt][kt][3],
                            A1[mt], A2[mt]);
#pragma unroll
            for (int nt = 0; nt < 4; nt++) {
                const u32* wr = Wf + ((48 + kt * 4 + nt) << 6) + lane * 2;
                u32 wb0 = wr[0], wb1 = wr[1];
                mma4(Ca[0][nt], A1[0], wb0, wb1);
                mma4(Ca[0][nt], A2[0], wb0, wb1);
                mma4(Ca[1][nt], A1[1], wb0, wb1);
                mma4(Ca[1][nt], A2[1], wb0, wb1);
            }
        }

        // ---- view: 59 -> 32 (tiles 64..95): kt0..3 chained from Ca, kt4..7 dir emb ----
#pragma unroll
        for (int nt = 0; nt < 4; nt++) {
            float bb0 = sm[128 + nt * 8 + 2 * tc], bb1 = sm[128 + nt * 8 + 2 * tc + 1];
#pragma unroll
            for (int mt = 0; mt < 2; mt++) {
                Cb[mt][nt][0] = bb0; Cb[mt][nt][1] = bb1;
                Cb[mt][nt][2] = bb0; Cb[mt][nt][3] = bb1;
            }
        }
#pragma unroll
        for (int kt = 0; kt < 8; kt++) {
#pragma unroll
            for (int mt = 0; mt < 2; mt++) {
                if (kt < 4) {
                    build_afrag(Ca[mt][kt][0], Ca[mt][kt][1], Ca[mt][kt][2], Ca[mt][kt][3],
                                A1[mt], A2[mt]);
                } else {
                    int cd0 = 8 * (kt - 4) + 2 * tc, cd1 = cd0 + 1;
                    float v0 = embcol(ex[2 * mt], ey[2 * mt], ez[2 * mt], cd0, 27);
                    float v1 = embcol(ex[2 * mt], ey[2 * mt], ez[2 * mt], cd1, 27);
                    float v2 = embcol(ex[2 * mt + 1], ey[2 * mt + 1], ez[2 * mt + 1], cd0, 27);
                    float v3 = embcol(ex[2 * mt + 1], ey[2 * mt + 1], ez[2 * mt + 1], cd1, 27);
                    build_afrag(v0, v1, v2, v3, A1[mt], A2[mt]);
                }
            }
#pragma unroll
            for (int nt = 0; nt < 4; nt++) {
                const u32* wr = Wf + ((64 + kt * 4 + nt) << 6) + lane * 2;
                u32 wb0 = wr[0], wb1 = wr[1];
                mma4(Cb[0][nt], A1[0], wb0, wb1);
                mma4(Cb[0][nt], A2[0], wb0, wb1);
                mma4(Cb[1][nt], A1[1], wb0, wb1);
                mma4(Cb[1][nt], A2[1], wb0, wb1);
            }
        }
#pragma unroll
        for (int mt = 0; mt < 2; mt++)
#pragma unroll
            for (int nt = 0; nt < 4; nt++)
#pragma unroll
                for (int r = 0; r < 4; r++)
                    Cb[mt][nt][r] = fmaxf(Cb[mt][nt][r], 0.f);

        // ---- epilogue: rgb partials per row + butterfly over tc group ----
        float rr[4][3];
#pragma unroll
        for (int mt = 0; mt < 2; mt++)
#pragma unroll
            for (int h = 0; h < 2; h++) {
                float a0 = 0.f, a1 = 0.f, a2 = 0.f;
#pragma unroll
                for (int nt = 0; nt < 4; nt++) {
                    int col0 = nt * 8 + 2 * tc, col1 = col0 + 1;
                    float v0 = Cb[mt][nt][2 * h], v1 = Cb[mt][nt][2 * h + 1];
                    a0 += v0 * sm[160 + col0 * 3 + 0] + v1 * sm[160 + col1 * 3 + 0];
                    a1 += v0 * sm[160 + col0 * 3 + 1] + v1 * sm[160 + col1 * 3 + 1];
                    a2 += v0 * sm[160 + col0 * 3 + 2] + v1 * sm[160 + col1 * 3 + 2];
                }
                rr[2 * mt + h][0] = a0; rr[2 * mt + h][1] = a1; rr[2 * mt + h][2] = a2;
            }
#pragma unroll
        for (int j = 0; j < 4; j++) {
#pragma unroll
            for (int ch = 0; ch < 3; ch++) {
                rr[j][ch] += __shfl_xor_sync(FULL, rr[j][ch], 1);
                rr[j][ch] += __shfl_xor_sync(FULL, rr[j][ch], 2);
            }
            sg[j] += __shfl_xor_sync(FULL, sg[j], 1);
            sg[j] += __shfl_xor_sync(FULL, sg[j], 2);
        }

        // thread tc writes row j=tc: row = 16*(tc>>1) + 8*(tc&1) + g
        {
            int row = 16 * (tc >> 1) + 8 * (tc & 1) + g;
            int nn = __shfl_sync(FULL, n, row);
            if (base + row < count) {
                out[3 * nn + 0] = rr[tc][0] + sm[256];
                out[3 * nn + 1] = rr[tc][1] + sm[257];
                out[3 * nn + 2] = rr[tc][2] + sm[258];
                out[(size_t)NPTS * 3 + nn] = sg[tc] + sm[259];
            }
        }
    }
}

extern "C" void kernel_launch(void* const* d_in, const int* in_sizes, int n_in,
                              void* d_out, int out_size) {
    (void)in_sizes; (void)n_in; (void)out_size;
    const float* pts = (const float*)d_in[0];
    const float* vd  = (const float*)d_in[1];
    const float* w0  = (const float*)d_in[2];
    const float* b0  = (const float*)d_in[3];
    const float* w1  = (const float*)d_in[4];
    const float* b1  = (const float*)d_in[5];
    const float* fw  = (const float*)d_in[6];
    const float* fb  = (const float*)d_in[7];
    const float* sw  = (const float*)d_in[8];
    const float* sb  = (const float*)d_in[9];
    const float* vw  = (const float*)d_in[10];
    const float* vb  = (const float*)d_in[11];
    const float* rw  = (const float*)d_in[12];
    const float* rb  = (const float*)d_in[13];

    k_index<<<512, 256>>>(pts);
    k_scan<<<1, 1024>>>();
    k_scatter<<<512, 256>>>();
    k_mlp<<<NM, 64>>>(pts, vd, w0, b0, w1, b1, fw, fb, sw, sb, vw, vb, rw, rb,
                      (float*)d_out);
}

// round 15
// speedup vs baseline: 1.0335x; 1.0335x over previous
#include <cuda_runtime.h>
#include <cuda_bf16.h>
#include <math.h>

#define NM      4096
#define NPTS    131072
#define GRES    16

typedef unsigned int u32;

// ---- scratch (no allocations allowed) ----
__device__ int g_cnt[NM];      // zero at load; re-zeroed by k_mlp each call
__device__ int g_start[NM];
__device__ int g_vox[NPTS];    // packed: voxel | (rank<<12)
__device__ int g_sorted[NPTS];

__global__ void k_index(const float* __restrict__ pts) {
    int n = blockIdx.x * blockDim.x + threadIdx.x;
    if (n >= NPTS) return;
    float x = pts[3 * n + 0], y = pts[3 * n + 1], z = pts[3 * n + 2];
    int ix = (int)fminf(fmaxf(x * (float)GRES, 0.f), (float)(GRES - 1));
    int iy = (int)fminf(fmaxf(y * (float)GRES, 0.f), (float)(GRES - 1));
    int iz = (int)fminf(fmaxf(z * (float)GRES, 0.f), (float)(GRES - 1));
    int v = ix * (GRES * GRES) + iy * GRES + iz;
    int r = atomicAdd(&g_cnt[v], 1);
    g_vox[n] = v | (r << 12);
}

__global__ void k_scan() {
    __shared__ int sh[1024];
    int t = threadIdx.x;
    int c0 = g_cnt[4 * t + 0], c1 = g_cnt[4 * t + 1];
    int c2 = g_cnt[4 * t + 2], c3 = g_cnt[4 * t + 3];
    int s = c0 + c1 + c2 + c3;
    sh[t] = s;
    __syncthreads();
    for (int d = 1; d < 1024; d <<= 1) {
        int v = (t >= d) ? sh[t - d] : 0;
        __syncthreads();
        sh[t] += v;
        __syncthreads();
    }
    int excl = sh[t] - s;
    g_start[4 * t + 0] = excl; excl += c0;
    g_start[4 * t + 1] = excl; excl += c1;
    g_start[4 * t + 2] = excl; excl += c2;
    g_start[4 * t + 3] = excl;
}

__global__ void k_scatter() {
    int n = blockIdx.x * blockDim.x + threadIdx.x;
    if (n >= NPTS) return;
    int pv = g_vox[n];
    g_sorted[g_start[pv & 4095] + (pv >> 12)] = n;
}

// ---- bf16 split helpers ----
__device__ __forceinline__ u32 pack_split(float f) {
    __nv_bfloat16 h1 = __float2bfloat16(f);
    float f1 = __bfloat162float(h1);
    __nv_bfloat16 h2 = __float2bfloat16(f - f1);
    return (u32)__bfloat16_as_ushort(h1) | ((u32)__bfloat16_as_ushort(h2) << 16);
}
// (bf16(v), bf16(v)) packed
__device__ __forceinline__ u32 dup2(float v) {
    u32 r;
    asm("cvt.rn.bf16x2.f32 %0, %1, %1;" : "=r"(r) : "f"(v));
    return r;
}
// (hi=0, lo=bf16(v - f32(bf16(v)))) : residual in low slot
__device__ __forceinline__ u32 res2(float v, u32 d) {
    float f1 = __uint_as_float(d << 16);
    float x2 = v - f1;
    u32 r;
    asm("cvt.rn.bf16x2.f32 %0, %1, %2;" : "=r"(r) : "f"(0.f), "f"(x2));
    return r;
}

// mma.sync m16n8k16 row.col f32 += bf16*bf16
__device__ __forceinline__ void mma4(float* C, const u32* a, u32 b0, u32 b1) {
    asm volatile(
        "mma.sync.aligned.m16n8k16.row.col.f32.bf16.bf16.f32 "
        "{%0,%1,%2,%3}, {%4,%5,%6,%7}, {%8,%9}, {%0,%1,%2,%3};"
        : "+f"(C[0]), "+f"(C[1]), "+f"(C[2]), "+f"(C[3])
        : "r"(a[0]), "r"(a[1]), "r"(a[2]), "r"(a[3]), "r"(b0), "r"(b1));
}

// A-frag build: v0=(row g,c0) v1=(row g,c1) v2=(row g+8,c0) v3=(row g+8,c1)
__device__ __forceinline__ void build_afrag(float v0, float v1, float v2, float v3,
                                            u32* P1, u32* P2) {
    P1[0] = dup2(v0); P1[1] = dup2(v2); P1[2] = dup2(v1); P1[3] = dup2(v3);
    P2[0] = res2(v0, P1[0]); P2[1] = res2(v2, P1[1]);
    P2[2] = res2(v1, P1[2]); P2[3] = res2(v3, P1[3]);
}

// ---- weight staging with input-slot permutation ----
// slot d holds real input neuron rd = blk*8 + (dl<4 ? 2dl : 2(dl-4)+1)
template<int DREAL, int DPAD>
__device__ __forceinline__ void stage_wf(const float* __restrict__ gsrc,
                                         u32* Wf, int tileOff, int tid) {
    const int total = 32 * DPAD;
    for (int i = tid; i < total; i += 64) {
        int no = i / DPAD;
        int d  = i % DPAD;
        int blk = d >> 3, dl = d & 7;
        int rd = blk * 8 + ((dl < 4) ? (2 * dl) : (2 * (dl - 4) + 1));
        float w = (rd < DREAL) ? gsrc[no * DREAL + rd] : 0.f;
        u32 pk = pack_split(w);
        int rg = dl >> 2;
        int tcb = dl & 3;
        int lane = ((no & 7) << 2) | tcb;
        int nt = no >> 3;
        Wf[(((tileOff + blk * 4 + nt) << 5) + lane) * 2 + rg] = pk;
    }
}

// embedding column: c 0..2 raw coord; 3.. -> sin/cos(2^k p); >=cmax -> 0
// single MUFU: cos(a) = sin(a + pi/2)
__device__ __forceinline__ float embcol(float x, float y, float z, int c, int cmax) {
    int u = c - 3;
    int k = u / 6;
    int comp = u - 6 * k;
    int c3 = (comp < 3) ? comp : comp - 3;
    float p = (c3 == 0) ? x : ((c3 == 1) ? y : z);
    float a = p * __uint_as_float((u32)(127 + k) << 23);
    if (comp >= 3) a += 1.5707963267948966f;
    float tv = __sinf(a);
    float raw = (c == 0) ? x : ((c == 1) ? y : z);
    float r = (c < 3) ? raw : tv;
    return (c < cmax) ? r : 0.f;
}

// one kt step: build A frags, preload 4 nt weights, issue pass-major MMAs
#define KT_STEP(C, TILE, kt) do {                                              \
    u32 wb_[4][2];                                                             \
    _Pragma("unroll")                                                          \
    for (int nt_ = 0; nt_ < 4; nt_++) {                                        \
        const u32* wr_ = Wf + (((TILE) + (kt) * 4 + nt_) << 6) + lane * 2;     \
        wb_[nt_][0] = wr_[0]; wb_[nt_][1] = wr_[1];                            \
    }                                                                          \
    _Pragma("unroll")                                                          \
    for (int nt_ = 0; nt_ < 4; nt_++) mma4(C[0][nt_], A1[0], wb_[nt_][0], wb_[nt_][1]); \
    _Pragma("unroll")                                                          \
    for (int nt_ = 0; nt_ < 4; nt_++) mma4(C[1][nt_], A1[1], wb_[nt_][0], wb_[nt_][1]); \
    _Pragma("unroll")                                                          \
    for (int nt_ = 0; nt_ < 4; nt_++) mma4(C[0][nt_], A2[0], wb_[nt_][0], wb_[nt_][1]); \
    _Pragma("unroll")                                                          \
    for (int nt_ = 0; nt_ < 4; nt_++) mma4(C[1][nt_], A2[1], wb_[nt_][0], wb_[nt_][1]); \
} while (0)

// smem layout (u32): Wf[6144] | small[264 floats]
#define OFF_SM  6144
#define SP_TOT  6408

__global__ void __launch_bounds__(64, 6) k_mlp(
    const float* __restrict__ pts, const float* __restrict__ vdirs,
    const float* __restrict__ w0, const float* __restrict__ b0,
    const float* __restrict__ w1, const float* __restrict__ b1,
    const float* __restrict__ fw, const float* __restrict__ fb,
    const float* __restrict__ sw, const float* __restrict__ sb,
    const float* __restrict__ vw, const float* __restrict__ vb,
    const float* __restrict__ rw, const float* __restrict__ rb,
    float* __restrict__ out)
{
    const int vox = blockIdx.x;
    const int tid = threadIdx.x;

    __shared__ __align__(16) u32 spool[SP_TOT];
    u32* Wf = spool;
    float* sm = (float*)(spool + OFF_SM);

    const int start = g_start[vox];
    const int count = g_cnt[vox];

    stage_wf<63, 64>(w0 + (size_t)vox * 2016, Wf, 0,  tid);
    stage_wf<32, 32>(w1 + (size_t)vox * 1024, Wf, 32, tid);
    stage_wf<32, 32>(fw + (size_t)vox * 1024, Wf, 48, tid);
    stage_wf<59, 64>(vw + (size_t)vox * 1888, Wf, 64, tid);

    for (int i = tid; i < 96; i += 64) {
        int c = i >> 5, d = i & 31;
        sm[160 + d * 3 + c] = rw[(size_t)vox * 96 + i];
    }
    if (tid < 32) {
        sm[tid]       = sw[(size_t)vox * 32 + tid];
        sm[32 + tid]  = b0[(size_t)vox * 32 + tid];
        sm[64 + tid]  = b1[(size_t)vox * 32 + tid];
        sm[96 + tid]  = fb[(size_t)vox * 32 + tid];
        sm[128 + tid] = vb[(size_t)vox * 32 + tid];
    }
    if (tid < 3) sm[256 + tid] = rb[(size_t)vox * 3 + tid];
    if (tid == 0) {
        sm[259] = sb[vox];
        g_cnt[vox] = 0;   // reset for next replay
    }
    __syncthreads();

    const int warp = tid >> 5, lane = tid & 31;
    const int g = lane >> 2, tc = lane & 3;
    const unsigned FULL = 0xFFFFFFFFu;

    for (int base = warp * 32; base < count; base += 64) {
        const int i = base + lane;
        const bool act = (i < count);
        int n = 0;
        float px = 0.f, py = 0.f, pz = 0.f, dvx = 0.f, dvy = 0.f, dvz = 0.f;
        if (act) {
            n = g_sorted[start + i];
            px = pts[3 * n + 0]; py = pts[3 * n + 1]; pz = pts[3 * n + 2];
            int ray = n >> 7;
            dvx = vdirs[3 * ray + 0]; dvy = vdirs[3 * ray + 1]; dvz = vdirs[3 * ray + 2];
        }

        // gather the 4 rows this thread contributes to: j -> row 16*(j>>1)+8*(j&1)+g
        float qx[4], qy[4], qz[4];
#pragma unroll
        for (int j = 0; j < 4; j++) {
            int src = 16 * (j >> 1) + 8 * (j & 1) + g;
            qx[j] = __shfl_sync(FULL, px, src);
            qy[j] = __shfl_sync(FULL, py, src);
            qz[j] = __shfl_sync(FULL, pz, src);
        }

        float Ca[2][4][4], Cb[2][4][4];
        u32 A1[2][4], A2[2][4];

        // ---- layer0: 63 -> 32 (tiles 0..31) ----
#pragma unroll
        for (int nt = 0; nt < 4; nt++) {
            float bb0 = sm[32 + nt * 8 + 2 * tc], bb1 = sm[32 + nt * 8 + 2 * tc + 1];
#pragma unroll
            for (int mt = 0; mt < 2; mt++) {
                Ca[mt][nt][0] = bb0; Ca[mt][nt][1] = bb1;
                Ca[mt][nt][2] = bb0; Ca[mt][nt][3] = bb1;
            }
        }
#pragma unroll
        for (int kt = 0; kt < 8; kt++) {
            int c0 = 8 * kt + 2 * tc, c1 = c0 + 1;
#pragma unroll
            for (int mt = 0; mt < 2; mt++) {
                float v0 = embcol(qx[2 * mt], qy[2 * mt], qz[2 * mt], c0, 63);
                float v1 = embcol(qx[2 * mt], qy[2 * mt], qz[2 * mt], c1, 63);
                float v2 = embcol(qx[2 * mt + 1], qy[2 * mt + 1], qz[2 * mt + 1], c0, 63);
                float v3 = embcol(qx[2 * mt + 1], qy[2 * mt + 1], qz[2 * mt + 1], c1, 63);
                build_afrag(v0, v1, v2, v3, A1[mt], A2[mt]);
            }
            KT_STEP(Ca, 0, kt);
        }
#pragma unroll
        for (int mt = 0; mt < 2; mt++)
#pragma unroll
            for (int nt = 0; nt < 4; nt++)
#pragma unroll
                for (int r = 0; r < 4; r++)
                    Ca[mt][nt][r] = fmaxf(Ca[mt][nt][r], 0.f);

        // ---- layer1: 32 -> 32 (tiles 32..47), chained from Ca ----
#pragma unroll
        for (int nt = 0; nt < 4; nt++) {
            float bb0 = sm[64 + nt * 8 + 2 * tc], bb1 = sm[64 + nt * 8 + 2 * tc + 1];
#pragma unroll
            for (int mt = 0; mt < 2; mt++) {
                Cb[mt][nt][0] = bb0; Cb[mt][nt][1] = bb1;
                Cb[mt][nt][2] = bb0; Cb[mt][nt][3] = bb1;
            }
        }
#pragma unroll
        for (int kt = 0; kt < 4; kt++) {
#pragma unroll
            for (int mt = 0; mt < 2; mt++)
                build_afrag(Ca[mt][kt][0], Ca[mt][kt][1], Ca[mt][kt][2], Ca[mt][kt][3],
                            A1[mt], A2[mt]);
            KT_STEP(Cb, 32, kt);
        }
#pragma unroll
        for (int mt = 0; mt < 2; mt++)
#pragma unroll
            for (int nt = 0; nt < 4; nt++)
#pragma unroll
                for (int r = 0; r < 4; r++)
                    Cb[mt][nt][r] = fmaxf(Cb[mt][nt][r], 0.f);

        // ---- sigma partials from h = Cb ----
        float sg[4] = {0.f, 0.f, 0.f, 0.f};
#pragma unroll
        for (int mt = 0; mt < 2; mt++)
#pragma unroll
            for (int h = 0; h < 2; h++) {
                float s = 0.f;
#pragma unroll
                for (int nt = 0; nt < 4; nt++) {
                    s += Cb[mt][nt][2 * h]     * sm[nt * 8 + 2 * tc];
                    s += Cb[mt][nt][2 * h + 1] * sm[nt * 8 + 2 * tc + 1];
                }
                sg[2 * mt + h] = s;
            }

        // ---- feat: 32 -> 32 (tiles 48..63), chained from Cb, NO relu ----
#pragma unroll
        for (int nt = 0; nt < 4; nt++) {
            float bb0 = sm[96 + nt * 8 + 2 * tc], bb1 = sm[96 + nt * 8 + 2 * tc + 1];
#pragma unroll
            for (int mt = 0; mt < 2; mt++) {
                Ca[mt][nt][0] = bb0; Ca[mt][nt][1] = bb1;
                Ca[mt][nt][2] = bb0; Ca[mt][nt][3] = bb1;
            }
        }
#pragma unroll
        for (int kt = 0; kt < 4; kt++) {
#pragma unroll
            for (int mt = 0; mt < 2; mt++)
                build_afrag(Cb[mt][kt][0], Cb[mt][kt][1], Cb[mt][kt][2], Cb[mt][kt][3],
                            A1[mt], A2[mt]);
            KT_STEP(Ca, 48, kt);
        }

        // ---- view: 59 -> 32 (tiles 64..95) ----
        // gather dir rows now (frees regs during earlier layers)
        float ex[4], ey[4], ez[4];
#pragma unroll
        for (int j = 0; j < 4; j++) {
            int src = 16 * (j >> 1) + 8 * (j & 1) + g;
            ex[j] = __shfl_sync(FULL, dvx, src);
            ey[j] = __shfl_sync(FULL, dvy, src);
            ez[j] = __shfl_sync(FULL, dvz, src);
        }
#pragma unroll
        for (int nt = 0; nt < 4; nt++) {
            float bb0 = sm[128 + nt * 8 + 2 * tc], bb1 = sm[128 + nt * 8 + 2 * tc + 1];
#pragma unroll
            for (int mt = 0; mt < 2; mt++) {
                Cb[mt][nt][0] = bb0; Cb[mt][nt][1] = bb1;
                Cb[mt][nt][2] = bb0; Cb[mt][nt][3] = bb1;
            }
        }
#pragma unroll
        for (int kt = 0; kt < 8; kt++) {
#pragma unroll
            for (int mt = 0; mt < 2; mt++) {
                if (kt < 4) {
                    build_afrag(Ca[mt][kt][0], Ca[mt][kt][1], Ca[mt][kt][2], Ca[mt][kt][3],
                                A1[mt], A2[mt]);
                } else {
                    int cd0 = 8 * (kt - 4) + 2 * tc, cd1 = cd0 + 1;
                    float v0 = embcol(ex[2 * mt], ey[2 * mt], ez[2 * mt], cd0, 27);
                    float v1 = embcol(ex[2 * mt], ey[2 * mt], ez[2 * mt], cd1, 27);
                    float v2 = embcol(ex[2 * mt + 1], ey[2 * mt + 1], ez[2 * mt + 1], cd0, 27);
                    float v3 = embcol(ex[2 * mt + 1], ey[2 * mt + 1], ez[2 * mt + 1], cd1, 27);
                    build_afrag(v0, v1, v2, v3, A1[mt], A2[mt]);
                }
            }
            KT_STEP(Cb, 64, kt);
        }
#pragma unroll
        for (int mt = 0; mt < 2; mt++)
#pragma unroll
            for (int nt = 0; nt < 4; nt++)
#pragma unroll
                for (int r = 0; r < 4; r++)
                    Cb[mt][nt][r] = fmaxf(Cb[mt][nt][r], 0.f);

        // ---- epilogue: rgb partials per row + butterfly over tc group ----
        float rr[4][3];
#pragma unroll
        for (int mt = 0; mt < 2; mt++)
#pragma unroll
            for (int h = 0; h < 2; h++) {
                float a0 = 0.f, a1 = 0.f, a2 = 0.f;
#pragma unroll
                for (int nt = 0; nt < 4; nt++) {
                    int col0 = nt * 8 + 2 * tc, col1 = col0 + 1;
                    float v0 = Cb[mt][nt][2 * h], v1 = Cb[mt][nt][2 * h + 1];
                    a0 += v0 * sm[160 + col0 * 3 + 0] + v1 * sm[160 + col1 * 3 + 0];
                    a1 += v0 * sm[160 + col0 * 3 + 1] + v1 * sm[160 + col1 * 3 + 1];
                    a2 += v0 * sm[160 + col0 * 3 + 2] + v1 * sm[160 + col1 * 3 + 2];
                }
                rr[2 * mt + h][0] = a0; rr[2 * mt + h][1] = a1; rr[2 * mt + h][2] = a2;
            }
#pragma unroll
        for (int j = 0; j < 4; j++) {
#pragma unroll
            for (int ch = 0; ch < 3; ch++) {
                rr[j][ch] += __shfl_xor_sync(FULL, rr[j][ch], 1);
                rr[j][ch] += __shfl_xor_sync(FULL, rr[j][ch], 2);
            }
            sg[j] += __shfl_xor_sync(FULL, sg[j], 1);
            sg[j] += __shfl_xor_sync(FULL, sg[j], 2);
        }

        // thread tc writes row j=tc: row = 16*(tc>>1) + 8*(tc&1) + g
        {
            int row = 16 * (tc >> 1) + 8 * (tc & 1) + g;
            int nn = __shfl_sync(FULL, n, row);
            if (base + row < count) {
                out[3 * nn + 0] = rr[tc][0] + sm[256];
                out[3 * nn + 1] = rr[tc][1] + sm[257];
                out[3 * nn + 2] = rr[tc][2] + sm[258];
                out[(size_t)NPTS * 3 + nn] = sg[tc] + sm[259];
            }
        }
    }
}

extern "C" void kernel_launch(void* const* d_in, const int* in_sizes, int n_in,
                              void* d_out, int out_size) {
    (void)in_sizes; (void)n_in; (void)out_size;
    const float* pts = (const float*)d_in[0];
    const float* vd  = (const float*)d_in[1];
    const float* w0  = (const float*)d_in[2];
    const float* b0  = (const float*)d_in[3];
    const float* w1  = (const float*)d_in[4];
    const float* b1  = (const float*)d_in[5];
    const float* fw  = (const float*)d_in[6];
    const float* fb  = (const float*)d_in[7];
    const float* sw  = (const float*)d_in[8];
    const float* sb  = (const float*)d_in[9];
    const float* vw  = (const float*)d_in[10];
    const float* vb  = (const float*)d_in[11];
    const float* rw  = (const float*)d_in[12];
    const float* rb  = (const float*)d_in[13];

    k_index<<<512, 256>>>(pts);
    k_scan<<<1, 1024>>>();
    k_scatter<<<512, 256>>>();
    k_mlp<<<NM, 64>>>(pts, vd, w0, b0, w1, b1, fw, fb, sw, sb, vw, vb, rw, rb,
                      (float*)d_out);
}

// round 16
// speedup vs baseline: 1.1372x; 1.1003x over previous
#include <cuda_runtime.h>
#include <cuda_bf16.h>
#include <math.h>

#define NM      4096
#define NPTS    131072
#define GRES    16

typedef unsigned int u32;

// ---- scratch (no allocations allowed) ----
__device__ int g_cnt[NM];      // zero at load; re-zeroed by k_mlp each call
__device__ int g_start[NM];
__device__ int g_vox[NPTS];    // packed: voxel | (rank<<12)
__device__ int g_sorted[NPTS];

__global__ void k_index(const float* __restrict__ pts) {
    int n = blockIdx.x * blockDim.x + threadIdx.x;
    if (n >= NPTS) return;
    float x = pts[3 * n + 0], y = pts[3 * n + 1], z = pts[3 * n + 2];
    int ix = (int)fminf(fmaxf(x * (float)GRES, 0.f), (float)(GRES - 1));
    int iy = (int)fminf(fmaxf(y * (float)GRES, 0.f), (float)(GRES - 1));
    int iz = (int)fminf(fmaxf(z * (float)GRES, 0.f), (float)(GRES - 1));
    int v = ix * (GRES * GRES) + iy * GRES + iz;
    int r = atomicAdd(&g_cnt[v], 1);
    g_vox[n] = v | (r << 12);
}

__global__ void k_scan() {
    __shared__ int sh[1024];
    int t = threadIdx.x;
    int c0 = g_cnt[4 * t + 0], c1 = g_cnt[4 * t + 1];
    int c2 = g_cnt[4 * t + 2], c3 = g_cnt[4 * t + 3];
    int s = c0 + c1 + c2 + c3;
    sh[t] = s;
    __syncthreads();
    for (int d = 1; d < 1024; d <<= 1) {
        int v = (t >= d) ? sh[t - d] : 0;
        __syncthreads();
        sh[t] += v;
        __syncthreads();
    }
    int excl = sh[t] - s;
    g_start[4 * t + 0] = excl; excl += c0;
    g_start[4 * t + 1] = excl; excl += c1;
    g_start[4 * t + 2] = excl; excl += c2;
    g_start[4 * t + 3] = excl;
}

__global__ void k_scatter() {
    int n = blockIdx.x * blockDim.x + threadIdx.x;
    if (n >= NPTS) return;
    int pv = g_vox[n];
    g_sorted[g_start[pv & 4095] + (pv >> 12)] = n;
}

// ---- bf16 split helpers ----
__device__ __forceinline__ u32 pack_split(float f) {
    __nv_bfloat16 h1 = __float2bfloat16(f);
    float f1 = __bfloat162float(h1);
    __nv_bfloat16 h2 = __float2bfloat16(f - f1);
    return (u32)__bfloat16_as_ushort(h1) | ((u32)__bfloat16_as_ushort(h2) << 16);
}
// (bf16(v), bf16(v)) packed
__device__ __forceinline__ u32 dup2(float v) {
    u32 r;
    asm("cvt.rn.bf16x2.f32 %0, %1, %1;" : "=r"(r) : "f"(v));
    return r;
}
// (hi=0, lo=bf16(v - f32(bf16(v)))) : residual in low slot
__device__ __forceinline__ u32 res2(float v, u32 d) {
    float f1 = __uint_as_float(d << 16);
    float x2 = v - f1;
    u32 r;
    asm("cvt.rn.bf16x2.f32 %0, %1, %2;" : "=r"(r) : "f"(0.f), "f"(x2));
    return r;
}

// mma.sync m16n8k16 row.col f32 += bf16*bf16
__device__ __forceinline__ void mma4(float* C, const u32* a, u32 b0, u32 b1) {
    asm volatile(
        "mma.sync.aligned.m16n8k16.row.col.f32.bf16.bf16.f32 "
        "{%0,%1,%2,%3}, {%4,%5,%6,%7}, {%8,%9}, {%0,%1,%2,%3};"
        : "+f"(C[0]), "+f"(C[1]), "+f"(C[2]), "+f"(C[3])
        : "r"(a[0]), "r"(a[1]), "r"(a[2]), "r"(a[3]), "r"(b0), "r"(b1));
}

// A-frag build: v0=(row g,c0) v1=(row g,c1) v2=(row g+8,c0) v3=(row g+8,c1)
__device__ __forceinline__ void build_afrag(float v0, float v1, float v2, float v3,
                                            u32* P1, u32* P2) {
    P1[0] = dup2(v0); P1[1] = dup2(v2); P1[2] = dup2(v1); P1[3] = dup2(v3);
    P2[0] = res2(v0, P1[0]); P2[1] = res2(v2, P1[1]);
    P2[2] = res2(v1, P1[2]); P2[3] = res2(v3, P1[3]);
}

// ---- weight staging with input-slot permutation ----
// slot d holds real input neuron rd = blk*8 + (dl<4 ? 2dl : 2(dl-4)+1)
template<int DREAL, int DPAD>
__device__ __forceinline__ void stage_wf(const float* __restrict__ gsrc,
                                         u32* Wf, int tileOff, int tid) {
    const int total = 32 * DPAD;
    for (int i = tid; i < total; i += 64) {
        int no = i / DPAD;
        int d  = i % DPAD;
        int blk = d >> 3, dl = d & 7;
        int rd = blk * 8 + ((dl < 4) ? (2 * dl) : (2 * (dl - 4) + 1));
        float w = (rd < DREAL) ? gsrc[no * DREAL + rd] : 0.f;
        u32 pk = pack_split(w);
        int rg = dl >> 2;
        int tcb = dl & 3;
        int lane = ((no & 7) << 2) | tcb;
        int nt = no >> 3;
        Wf[(((tileOff + blk * 4 + nt) << 5) + lane) * 2 + rg] = pk;
    }
}

// embedding column: c 0..2 raw coord; 3.. -> sin/cos(2^k p); >=cmax -> 0
// single MUFU: cos(a) = sin(a + pi/2)
__device__ __forceinline__ float embcol(float x, float y, float z, int c, int cmax) {
    int u = c - 3;
    int k = u / 6;
    int comp = u - 6 * k;
    int c3 = (comp < 3) ? comp : comp - 3;
    float p = (c3 == 0) ? x : ((c3 == 1) ? y : z);
    float a = p * __uint_as_float((u32)(127 + k) << 23);
    if (comp >= 3) a += 1.5707963267948966f;
    float tv = __sinf(a);
    float raw = (c == 0) ? x : ((c == 1) ? y : z);
    float r = (c < 3) ? raw : tv;
    return (c < cmax) ? r : 0.f;
}

// one kt step: build A frags, preload 4 nt weights, issue pass-major MMAs
#define KT_STEP(C, TILE, kt) do {                                              \
    u32 wb_[4][2];                                                             \
    _Pragma("unroll")                                                          \
    for (int nt_ = 0; nt_ < 4; nt_++) {                                        \
        const u32* wr_ = Wf + (((TILE) + (kt) * 4 + nt_) << 6) + lane * 2;     \
        wb_[nt_][0] = wr_[0]; wb_[nt_][1] = wr_[1];                            \
    }                                                                          \
    _Pragma("unroll")                                                          \
    for (int nt_ = 0; nt_ < 4; nt_++) mma4(C[0][nt_], A1[0], wb_[nt_][0], wb_[nt_][1]); \
    _Pragma("unroll")                                                          \
    for (int nt_ = 0; nt_ < 4; nt_++) mma4(C[1][nt_], A1[1], wb_[nt_][0], wb_[nt_][1]); \
    _Pragma("unroll")                                                          \
    for (int nt_ = 0; nt_ < 4; nt_++) mma4(C[0][nt_], A2[0], wb_[nt_][0], wb_[nt_][1]); \
    _Pragma("unroll")                                                          \
    for (int nt_ = 0; nt_ < 4; nt_++) mma4(C[1][nt_], A2[1], wb_[nt_][0], wb_[nt_][1]); \
} while (0)

// smem layout (u32): Wf[6144] | small[264 floats]
#define OFF_SM  6144
#define SP_TOT  6408

__global__ void __launch_bounds__(64, 7) k_mlp(
    const float* __restrict__ pts, const float* __restrict__ vdirs,
    const float* __restrict__ w0, const float* __restrict__ b0,
    const float* __restrict__ w1, const float* __restrict__ b1,
    const float* __restrict__ fw, const float* __restrict__ fb,
    const float* __restrict__ sw, const float* __restrict__ sb,
    const float* __restrict__ vw, const float* __restrict__ vb,
    const float* __restrict__ rw, const float* __restrict__ rb,
    float* __restrict__ out)
{
    const int vox = blockIdx.x;
    const int tid = threadIdx.x;

    __shared__ __align__(16) u32 spool[SP_TOT];
    u32* Wf = spool;
    float* sm = (float*)(spool + OFF_SM);

    const int start = g_start[vox];
    const int count = g_cnt[vox];

    stage_wf<63, 64>(w0 + (size_t)vox * 2016, Wf, 0,  tid);
    stage_wf<32, 32>(w1 + (size_t)vox * 1024, Wf, 32, tid);
    stage_wf<32, 32>(fw + (size_t)vox * 1024, Wf, 48, tid);
    stage_wf<59, 64>(vw + (size_t)vox * 1888, Wf, 64, tid);

    for (int i = tid; i < 96; i += 64) {
        int c = i >> 5, d = i & 31;
        sm[160 + d * 3 + c] = rw[(size_t)vox * 96 + i];
    }
    if (tid < 32) {
        sm[tid]       = sw[(size_t)vox * 32 + tid];
        sm[32 + tid]  = b0[(size_t)vox * 32 + tid];
        sm[64 + tid]  = b1[(size_t)vox * 32 + tid];
        sm[96 + tid]  = fb[(size_t)vox * 32 + tid];
        sm[128 + tid] = vb[(size_t)vox * 32 + tid];
    }
    if (tid < 3) sm[256 + tid] = rb[(size_t)vox * 3 + tid];
    if (tid == 0) {
        sm[259] = sb[vox];
        g_cnt[vox] = 0;   // reset for next replay
    }
    __syncthreads();

    const int warp = tid >> 5, lane = tid & 31;
    const int g = lane >> 2, tc = lane & 3;
    const unsigned FULL = 0xFFFFFFFFu;

    for (int base = warp * 32; base < count; base += 64) {
        const int i = base + lane;
        const bool act = (i < count);
        int n = 0;
        float px = 0.f, py = 0.f, pz = 0.f, dvx = 0.f, dvy = 0.f, dvz = 0.f;
        if (act) {
            n = g_sorted[start + i];
            px = pts[3 * n + 0]; py = pts[3 * n + 1]; pz = pts[3 * n + 2];
            int ray = n >> 7;
            dvx = vdirs[3 * ray + 0]; dvy = vdirs[3 * ray + 1]; dvz = vdirs[3 * ray + 2];
        }

        // gather the 4 rows this thread contributes to: j -> row 16*(j>>1)+8*(j&1)+g
        float qx[4], qy[4], qz[4];
#pragma unroll
        for (int j = 0; j < 4; j++) {
            int src = 16 * (j >> 1) + 8 * (j & 1) + g;
            qx[j] = __shfl_sync(FULL, px, src);
            qy[j] = __shfl_sync(FULL, py, src);
            qz[j] = __shfl_sync(FULL, pz, src);
        }

        float Ca[2][4][4], Cb[2][4][4];
        u32 A1[2][4], A2[2][4];

        // ---- layer0: 63 -> 32 (tiles 0..31) ----
#pragma unroll
        for (int nt = 0; nt < 4; nt++) {
            float bb0 = sm[32 + nt * 8 + 2 * tc], bb1 = sm[32 + nt * 8 + 2 * tc + 1];
#pragma unroll
            for (int mt = 0; mt < 2; mt++) {
                Ca[mt][nt][0] = bb0; Ca[mt][nt][1] = bb1;
                Ca[mt][nt][2] = bb0; Ca[mt][nt][3] = bb1;
            }
        }
#pragma unroll
        for (int kt = 0; kt < 8; kt++) {
            int c0 = 8 * kt + 2 * tc, c1 = c0 + 1;
#pragma unroll
            for (int mt = 0; mt < 2; mt++) {
                float v0 = embcol(qx[2 * mt], qy[2 * mt], qz[2 * mt], c0, 63);
                float v1 = embcol(qx[2 * mt], qy[2 * mt], qz[2 * mt], c1, 63);
                float v2 = embcol(qx[2 * mt + 1], qy[2 * mt + 1], qz[2 * mt + 1], c0, 63);
                float v3 = embcol(qx[2 * mt + 1], qy[2 * mt + 1], qz[2 * mt + 1], c1, 63);
                build_afrag(v0, v1, v2, v3, A1[mt], A2[mt]);
            }
            KT_STEP(Ca, 0, kt);
        }
#pragma unroll
        for (int mt = 0; mt < 2; mt++)
#pragma unroll
            for (int nt = 0; nt < 4; nt++)
#pragma unroll
                for (int r = 0; r < 4; r++)
                    Ca[mt][nt][r] = fmaxf(Ca[mt][nt][r], 0.f);

        // ---- layer1: 32 -> 32 (tiles 32..47), chained from Ca ----
#pragma unroll
        for (int nt = 0; nt < 4; nt++) {
            float bb0 = sm[64 + nt * 8 + 2 * tc], bb1 = sm[64 + nt * 8 + 2 * tc + 1];
#pragma unroll
            for (int mt = 0; mt < 2; mt++) {
                Cb[mt][nt][0] = bb0; Cb[mt][nt][1] = bb1;
                Cb[mt][nt][2] = bb0; Cb[mt][nt][3] = bb1;
            }
        }
#pragma unroll
        for (int kt = 0; kt < 4; kt++) {
#pragma unroll
            for (int mt = 0; mt < 2; mt++)
                build_afrag(Ca[mt][kt][0], Ca[mt][kt][1], Ca[mt][kt][2], Ca[mt][kt][3],
                            A1[mt], A2[mt]);
            KT_STEP(Cb, 32, kt);
        }
#pragma unroll
        for (int mt = 0; mt < 2; mt++)
#pragma unroll
            for (int nt = 0; nt < 4; nt++)
#pragma unroll
                for (int r = 0; r < 4; r++)
                    Cb[mt][nt][r] = fmaxf(Cb[mt][nt][r], 0.f);

        // ---- sigma partials from h = Cb ----
        float sg[4] = {0.f, 0.f, 0.f, 0.f};
#pragma unroll
        for (int mt = 0; mt < 2; mt++)
#pragma unroll
            for (int h = 0; h < 2; h++) {
                float s = 0.f;
#pragma unroll
                for (int nt = 0; nt < 4; nt++) {
                    s += Cb[mt][nt][2 * h]     * sm[nt * 8 + 2 * tc];
                    s += Cb[mt][nt][2 * h + 1] * sm[nt * 8 + 2 * tc + 1];
                }
                sg[2 * mt + h] = s;
            }

        // ---- feat: 32 -> 32 (tiles 48..63), chained from Cb, NO relu ----
#pragma unroll
        for (int nt = 0; nt < 4; nt++) {
            float bb0 = sm[96 + nt * 8 + 2 * tc], bb1 = sm[96 + nt * 8 + 2 * tc + 1];
#pragma unroll
            for (int mt = 0; mt < 2; mt++) {
                Ca[mt][nt][0] = bb0; Ca[mt][nt][1] = bb1;
                Ca[mt][nt][2] = bb0; Ca[mt][nt][3] = bb1;
            }
        }
#pragma unroll
        for (int kt = 0; kt < 4; kt++) {
#pragma unroll
            for (int mt = 0; mt < 2; mt++)
                build_afrag(Cb[mt][kt][0], Cb[mt][kt][1], Cb[mt][kt][2], Cb[mt][kt][3],
                            A1[mt], A2[mt]);
            KT_STEP(Ca, 48, kt);
        }

        // ---- view: 59 -> 32 (tiles 64..95) ----
        float ex[4], ey[4], ez[4];
#pragma unroll
        for (int j = 0; j < 4; j++) {
            int src = 16 * (j >> 1) + 8 * (j & 1) + g;
            ex[j] = __shfl_sync(FULL, dvx, src);
            ey[j] = __shfl_sync(FULL, dvy, src);
            ez[j] = __shfl_sync(FULL, dvz, src);
        }
#pragma unroll
        for (int nt = 0; nt < 4; nt++) {
            float bb0 = sm[128 + nt * 8 + 2 * tc], bb1 = sm[128 + nt * 8 + 2 * tc + 1];
#pragma unroll
            for (int mt = 0; mt < 2; mt++) {
                Cb[mt][nt][0] = bb0; Cb[mt][nt][1] = bb1;
                Cb[mt][nt][2] = bb0; Cb[mt][nt][3] = bb1;
            }
        }
#pragma unroll
        for (int kt = 0; kt < 8; kt++) {
#pragma unroll
            for (int mt = 0; mt < 2; mt++) {
                if (kt < 4) {
                    build_afrag(Ca[mt][kt][0], Ca[mt][kt][1], Ca[mt][kt][2], Ca[mt][kt][3],
                                A1[mt], A2[mt]);
                } else {
                    int cd0 = 8 * (kt - 4) + 2 * tc, cd1 = cd0 + 1;
                    float v0 = embcol(ex[2 * mt], ey[2 * mt], ez[2 * mt], cd0, 27);
                    float v1 = embcol(ex[2 * mt], ey[2 * mt], ez[2 * mt], cd1, 27);
                    float v2 = embcol(ex[2 * mt + 1], ey[2 * mt + 1], ez[2 * mt + 1], cd0, 27);
                    float v3 = embcol(ex[2 * mt + 1], ey[2 * mt + 1], ez[2 * mt + 1], cd1, 27);
                    build_afrag(v0, v1, v2, v3, A1[mt], A2[mt]);
                }
            }
            KT_STEP(Cb, 64, kt);
        }
#pragma unroll
        for (int mt = 0; mt < 2; mt++)
#pragma unroll
            for (int nt = 0; nt < 4; nt++)
#pragma unroll
                for (int r = 0; r < 4; r++)
                    Cb[mt][nt][r] = fmaxf(Cb[mt][nt][r], 0.f);

        // ---- epilogue: rgb partials per row + butterfly over tc group ----
        float rr[4][3];
#pragma unroll
        for (int mt = 0; mt < 2; mt++)
#pragma unroll
            for (int h = 0; h < 2; h++) {
                float a0 = 0.f, a1 = 0.f, a2 = 0.f;
#pragma unroll
                for (int nt = 0; nt < 4; nt++) {
                    int col0 = nt * 8 + 2 * tc, col1 = col0 + 1;
                    float v0 = Cb[mt][nt][2 * h], v1 = Cb[mt][nt][2 * h + 1];
                    a0 += v0 * sm[160 + col0 * 3 + 0] + v1 * sm[160 + col1 * 3 + 0];
                    a1 += v0 * sm[160 + col0 * 3 + 1] + v1 * sm[160 + col1 * 3 + 1];
                    a2 += v0 * sm[160 + col0 * 3 + 2] + v1 * sm[160 + col1 * 3 + 2];
                }
                rr[2 * mt + h][0] = a0; rr[2 * mt + h][1] = a1; rr[2 * mt + h][2] = a2;
            }
#pragma unroll
        for (int j = 0; j < 4; j++) {
#pragma unroll
            for (int ch = 0; ch < 3; ch++) {
                rr[j][ch] += __shfl_xor_sync(FULL, rr[j][ch], 1);
                rr[j][ch] += __shfl_xor_sync(FULL, rr[j][ch], 2);
            }
            sg[j] += __shfl_xor_sync(FULL, sg[j], 1);
            sg[j] += __shfl_xor_sync(FULL, sg[j], 2);
        }

        // thread tc writes row j=tc: row = 16*(tc>>1) + 8*(tc&1) + g
        {
            int row = 16 * (tc >> 1) + 8 * (tc & 1) + g;
            int nn = __shfl_sync(FULL, n, row);
            if (base + row < count) {
                out[3 * nn + 0] = rr[tc][0] + sm[256];
                out[3 * nn + 1] = rr[tc][1] + sm[257];
                out[3 * nn + 2] = rr[tc][2] + sm[258];
                out[(size_t)NPTS * 3 + nn] = sg[tc] + sm[259];
            }
        }
    }
}

extern "C" void kernel_launch(void* const* d_in, const int* in_sizes, int n_in,
                              void* d_out, int out_size) {
    (void)in_sizes; (void)n_in; (void)out_size;
    const float* pts = (const float*)d_in[0];
    const float* vd  = (const float*)d_in[1];
    const float* w0  = (const float*)d_in[2];
    const float* b0  = (const float*)d_in[3];
    const float* w1  = (const float*)d_in[4];
    const float* b1  = (const float*)d_in[5];
    const float* fw  = (const float*)d_in[6];
    const float* fb  = (const float*)d_in[7];
    const float* sw  = (const float*)d_in[8];
    const float* sb  = (const float*)d_in[9];
    const float* vw  = (const float*)d_in[10];
    const float* vb  = (const float*)d_in[11];
    const float* rw  = (const float*)d_in[12];
    const float* rb  = (const float*)d_in[13];

    k_index<<<512, 256>>>(pts);
    k_scan<<<1, 1024>>>();
    k_scatter<<<512, 256>>>();
    k_mlp<<<NM, 64>>>(pts, vd, w0, b0, w1, b1, fw, fb, sw, sb, vw, vb, rw, rb,
                      (float*)d_out);
}

// round 17
// speedup vs baseline: 1.1443x; 1.0063x over previous
#include <cuda_runtime.h>
#include <cuda_bf16.h>
#include <math.h>

#define NM      4096
#define NPTS    131072
#define GRES    16

typedef unsigned int u32;

// ---- scratch (no allocations allowed) ----
__device__ int g_cnt[NM];      // zero at load; re-zeroed by k_mlp each call
__device__ int g_start[NM];
__device__ int g_vox[NPTS];    // packed: voxel | (rank<<12)
__device__ int g_sorted[NPTS];

__global__ void k_index(const float* __restrict__ pts) {
    int n = blockIdx.x * blockDim.x + threadIdx.x;
    if (n >= NPTS) return;
    float x = pts[3 * n + 0], y = pts[3 * n + 1], z = pts[3 * n + 2];
    int ix = (int)fminf(fmaxf(x * (float)GRES, 0.f), (float)(GRES - 1));
    int iy = (int)fminf(fmaxf(y * (float)GRES, 0.f), (float)(GRES - 1));
    int iz = (int)fminf(fmaxf(z * (float)GRES, 0.f), (float)(GRES - 1));
    int v = ix * (GRES * GRES) + iy * GRES + iz;
    int r = atomicAdd(&g_cnt[v], 1);
    g_vox[n] = v | (r << 12);
}

__global__ void k_scan() {
    __shared__ int sh[1024];
    int t = threadIdx.x;
    int c0 = g_cnt[4 * t + 0], c1 = g_cnt[4 * t + 1];
    int c2 = g_cnt[4 * t + 2], c3 = g_cnt[4 * t + 3];
    int s = c0 + c1 + c2 + c3;
    sh[t] = s;
    __syncthreads();
    for (int d = 1; d < 1024; d <<= 1) {
        int v = (t >= d) ? sh[t - d] : 0;
        __syncthreads();
        sh[t] += v;
        __syncthreads();
    }
    int excl = sh[t] - s;
    g_start[4 * t + 0] = excl; excl += c0;
    g_start[4 * t + 1] = excl; excl += c1;
    g_start[4 * t + 2] = excl; excl += c2;
    g_start[4 * t + 3] = excl;
}

__global__ void k_scatter() {
    int n = blockIdx.x * blockDim.x + threadIdx.x;
    if (n >= NPTS) return;
    int pv = g_vox[n];
    g_sorted[g_start[pv & 4095] + (pv >> 12)] = n;
}

// ---- bf16 split helpers ----
__device__ __forceinline__ u32 pack_split(float f) {
    __nv_bfloat16 h1 = __float2bfloat16(f);
    float f1 = __bfloat162float(h1);
    __nv_bfloat16 h2 = __float2bfloat16(f - f1);
    return (u32)__bfloat16_as_ushort(h1) | ((u32)__bfloat16_as_ushort(h2) << 16);
}
// (bf16(v), bf16(v)) packed
__device__ __forceinline__ u32 dup2(float v) {
    u32 r;
    asm("cvt.rn.bf16x2.f32 %0, %1, %1;" : "=r"(r) : "f"(v));
    return r;
}
// (hi=0, lo=bf16(v - f32(bf16(v)))) : residual in low slot
__device__ __forceinline__ u32 res2(float v, u32 d) {
    float f1 = __uint_as_float(d << 16);
    float x2 = v - f1;
    u32 r;
    asm("cvt.rn.bf16x2.f32 %0, %1, %2;" : "=r"(r) : "f"(0.f), "f"(x2));
    return r;
}

// mma.sync m16n8k16 row.col f32 += bf16*bf16
__device__ __forceinline__ void mma4(float* C, const u32* a, u32 b0, u32 b1) {
    asm volatile(
        "mma.sync.aligned.m16n8k16.row.col.f32.bf16.bf16.f32 "
        "{%0,%1,%2,%3}, {%4,%5,%6,%7}, {%8,%9}, {%0,%1,%2,%3};"
        : "+f"(C[0]), "+f"(C[1]), "+f"(C[2]), "+f"(C[3])
        : "r"(a[0]), "r"(a[1]), "r"(a[2]), "r"(a[3]), "r"(b0), "r"(b1));
}

// A-frag build: v0=(row g,c0) v1=(row g,c1) v2=(row g+8,c0) v3=(row g+8,c1)
__device__ __forceinline__ void build_afrag(float v0, float v1, float v2, float v3,
                                            u32* P1, u32* P2) {
    P1[0] = dup2(v0); P1[1] = dup2(v2); P1[2] = dup2(v1); P1[3] = dup2(v3);
    P2[0] = res2(v0, P1[0]); P2[1] = res2(v2, P1[1]);
    P2[2] = res2(v1, P1[2]); P2[3] = res2(v3, P1[3]);
}

// ---- weight staging with input-slot permutation ----
// slot d holds real input neuron rd = blk*8 + (dl<4 ? 2dl : 2(dl-4)+1)
template<int DREAL, int DPAD>
__device__ __forceinline__ void stage_wf(const float* __restrict__ gsrc,
                                         u32* Wf, int tileOff, int tid) {
    const int total = 32 * DPAD;
    for (int i = tid; i < total; i += 64) {
        int no = i / DPAD;
        int d  = i % DPAD;
        int blk = d >> 3, dl = d & 7;
        int rd = blk * 8 + ((dl < 4) ? (2 * dl) : (2 * (dl - 4) + 1));
        float w = (rd < DREAL) ? gsrc[no * DREAL + rd] : 0.f;
        u32 pk = pack_split(w);
        int rg = dl >> 2;
        int tcb = dl & 3;
        int lane = ((no & 7) << 2) | tcb;
        int nt = no >> 3;
        Wf[(((tileOff + blk * 4 + nt) << 5) + lane) * 2 + rg] = pk;
    }
}

// embedding column: c 0..2 raw coord; 3.. -> sin/cos(2^k p); >=cmax -> 0
// single MUFU: cos(a) = sin(a + pi/2)
__device__ __forceinline__ float embcol(float x, float y, float z, int c, int cmax) {
    int u = c - 3;
    int k = u / 6;
    int comp = u - 6 * k;
    int c3 = (comp < 3) ? comp : comp - 3;
    float p = (c3 == 0) ? x : ((c3 == 1) ? y : z);
    float a = p * __uint_as_float((u32)(127 + k) << 23);
    if (comp >= 3) a += 1.5707963267948966f;
    float tv = __sinf(a);
    float raw = (c == 0) ? x : ((c == 1) ? y : z);
    float r = (c < 3) ? raw : tv;
    return (c < cmax) ? r : 0.f;
}

// one kt step: build A frags, preload 4 nt weights, issue pass-major MMAs
#define KT_STEP(C, TILE, kt) do {                                              \
    u32 wb_[4][2];                                                             \
    _Pragma("unroll")                                                          \
    for (int nt_ = 0; nt_ < 4; nt_++) {                                        \
        const u32* wr_ = Wf + (((TILE) + (kt) * 4 + nt_) << 6) + lane * 2;     \
        wb_[nt_][0] = wr_[0]; wb_[nt_][1] = wr_[1];                            \
    }                                                                          \
    _Pragma("unroll")                                                          \
    for (int nt_ = 0; nt_ < 4; nt_++) mma4(C[0][nt_], A1[0], wb_[nt_][0], wb_[nt_][1]); \
    _Pragma("unroll")                                                          \
    for (int nt_ = 0; nt_ < 4; nt_++) mma4(C[1][nt_], A1[1], wb_[nt_][0], wb_[nt_][1]); \
    _Pragma("unroll")                                                          \
    for (int nt_ = 0; nt_ < 4; nt_++) mma4(C[0][nt_], A2[0], wb_[nt_][0], wb_[nt_][1]); \
    _Pragma("unroll")                                                          \
    for (int nt_ = 0; nt_ < 4; nt_++) mma4(C[1][nt_], A2[1], wb_[nt_][0], wb_[nt_][1]); \
} while (0)

// smem layout (u32): Wf[6144] | small[264 floats]
#define OFF_SM  6144
#define SP_TOT  6408

__global__ void __launch_bounds__(64, 8) k_mlp(
    const float* __restrict__ pts, const float* __restrict__ vdirs,
    const float* __restrict__ w0, const float* __restrict__ b0,
    const float* __restrict__ w1, const float* __restrict__ b1,
    const float* __restrict__ fw, const float* __restrict__ fb,
    const float* __restrict__ sw, const float* __restrict__ sb,
    const float* __restrict__ vw, const float* __restrict__ vb,
    const float* __restrict__ rw, const float* __restrict__ rb,
    float* __restrict__ out)
{
    const int vox = blockIdx.x;
    const int tid = threadIdx.x;

    __shared__ __align__(16) u32 spool[SP_TOT];
    u32* Wf = spool;
    float* sm = (float*)(spool + OFF_SM);

    const int start = g_start[vox];
    const int count = g_cnt[vox];

    stage_wf<63, 64>(w0 + (size_t)vox * 2016, Wf, 0,  tid);
    stage_wf<32, 32>(w1 + (size_t)vox * 1024, Wf, 32, tid);
    stage_wf<32, 32>(fw + (size_t)vox * 1024, Wf, 48, tid);
    stage_wf<59, 64>(vw + (size_t)vox * 1888, Wf, 64, tid);

    for (int i = tid; i < 96; i += 64) {
        int c = i >> 5, d = i & 31;
        sm[160 + d * 3 + c] = rw[(size_t)vox * 96 + i];
    }
    if (tid < 32) {
        sm[tid]       = sw[(size_t)vox * 32 + tid];
        sm[32 + tid]  = b0[(size_t)vox * 32 + tid];
        sm[64 + tid]  = b1[(size_t)vox * 32 + tid];
        sm[96 + tid]  = fb[(size_t)vox * 32 + tid];
        sm[128 + tid] = vb[(size_t)vox * 32 + tid];
    }
    if (tid < 3) sm[256 + tid] = rb[(size_t)vox * 3 + tid];
    if (tid == 0) {
        sm[259] = sb[vox];
        g_cnt[vox] = 0;   // reset for next replay
    }
    __syncthreads();

    const int warp = tid >> 5, lane = tid & 31;
    const int g = lane >> 2, tc = lane & 3;
    const unsigned FULL = 0xFFFFFFFFu;

    for (int base = warp * 32; base < count; base += 64) {
        const int i = base + lane;
        const bool act = (i < count);
        int n = 0;
        float px = 0.f, py = 0.f, pz = 0.f, dvx = 0.f, dvy = 0.f, dvz = 0.f;
        if (act) {
            n = g_sorted[start + i];
            px = pts[3 * n + 0]; py = pts[3 * n + 1]; pz = pts[3 * n + 2];
            int ray = n >> 7;
            dvx = vdirs[3 * ray + 0]; dvy = vdirs[3 * ray + 1]; dvz = vdirs[3 * ray + 2];
        }

        // gather the 4 rows this thread contributes to: j -> row 16*(j>>1)+8*(j&1)+g
        float qx[4], qy[4], qz[4];
#pragma unroll
        for (int j = 0; j < 4; j++) {
            int src = 16 * (j >> 1) + 8 * (j & 1) + g;
            qx[j] = __shfl_sync(FULL, px, src);
            qy[j] = __shfl_sync(FULL, py, src);
            qz[j] = __shfl_sync(FULL, pz, src);
        }

        float Ca[2][4][4], Cb[2][4][4];
        u32 A1[2][4], A2[2][4];

        // ---- layer0: 63 -> 32 (tiles 0..31) ----
#pragma unroll
        for (int nt = 0; nt < 4; nt++) {
            float bb0 = sm[32 + nt * 8 + 2 * tc], bb1 = sm[32 + nt * 8 + 2 * tc + 1];
#pragma unroll
            for (int mt = 0; mt < 2; mt++) {
                Ca[mt][nt][0] = bb0; Ca[mt][nt][1] = bb1;
                Ca[mt][nt][2] = bb0; Ca[mt][nt][3] = bb1;
            }
        }
#pragma unroll
        for (int kt = 0; kt < 8; kt++) {
            int c0 = 8 * kt + 2 * tc, c1 = c0 + 1;
#pragma unroll
            for (int mt = 0; mt < 2; mt++) {
                float v0 = embcol(qx[2 * mt], qy[2 * mt], qz[2 * mt], c0, 63);
                float v1 = embcol(qx[2 * mt], qy[2 * mt], qz[2 * mt], c1, 63);
                float v2 = embcol(qx[2 * mt + 1], qy[2 * mt + 1], qz[2 * mt + 1], c0, 63);
                float v3 = embcol(qx[2 * mt + 1], qy[2 * mt + 1], qz[2 * mt + 1], c1, 63);
                build_afrag(v0, v1, v2, v3, A1[mt], A2[mt]);
            }
            KT_STEP(Ca, 0, kt);
        }
#pragma unroll
        for (int mt = 0; mt < 2; mt++)
#pragma unroll
            for (int nt = 0; nt < 4; nt++)
#pragma unroll
                for (int r = 0; r < 4; r++)
                    Ca[mt][nt][r] = fmaxf(Ca[mt][nt][r], 0.f);

        // ---- layer1: 32 -> 32 (tiles 32..47), chained from Ca ----
#pragma unroll
        for (int nt = 0; nt < 4; nt++) {
            float bb0 = sm[64 + nt * 8 + 2 * tc], bb1 = sm[64 + nt * 8 + 2 * tc + 1];
#pragma unroll
            for (int mt = 0; mt < 2; mt++) {
                Cb[mt][nt][0] = bb0; Cb[mt][nt][1] = bb1;
                Cb[mt][nt][2] = bb0; Cb[mt][nt][3] = bb1;
            }
        }
#pragma unroll
        for (int kt = 0; kt < 4; kt++) {
#pragma unroll
            for (int mt = 0; mt < 2; mt++)
                build_afrag(Ca[mt][kt][0], Ca[mt][kt][1], Ca[mt][kt][2], Ca[mt][kt][3],
                            A1[mt], A2[mt]);
            KT_STEP(Cb, 32, kt);
        }
#pragma unroll
        for (int mt = 0; mt < 2; mt++)
#pragma unroll
            for (int nt = 0; nt < 4; nt++)
#pragma unroll
                for (int r = 0; r < 4; r++)
                    Cb[mt][nt][r] = fmaxf(Cb[mt][nt][r], 0.f);

        // ---- sigma partials from h = Cb ----
        float sg[4] = {0.f, 0.f, 0.f, 0.f};
#pragma unroll
        for (int mt = 0; mt < 2; mt++)
#pragma unroll
            for (int h = 0; h < 2; h++) {
                float s = 0.f;
#pragma unroll
                for (int nt = 0; nt < 4; nt++) {
                    s += Cb[mt][nt][2 * h]     * sm[nt * 8 + 2 * tc];
                    s += Cb[mt][nt][2 * h + 1] * sm[nt * 8 + 2 * tc + 1];
                }
                sg[2 * mt + h] = s;
            }

        // ---- feat: 32 -> 32 (tiles 48..63), chained from Cb, NO relu ----
#pragma unroll
        for (int nt = 0; nt < 4; nt++) {
            float bb0 = sm[96 + nt * 8 + 2 * tc], bb1 = sm[96 + nt * 8 + 2 * tc + 1];
#pragma unroll
            for (int mt = 0; mt < 2; mt++) {
                Ca[mt][nt][0] = bb0; Ca[mt][nt][1] = bb1;
                Ca[mt][nt][2] = bb0; Ca[mt][nt][3] = bb1;
            }
        }
#pragma unroll
        for (int kt = 0; kt < 4; kt++) {
#pragma unroll
            for (int mt = 0; mt < 2; mt++)
                build_afrag(Cb[mt][kt][0], Cb[mt][kt][1], Cb[mt][kt][2], Cb[mt][kt][3],
                            A1[mt], A2[mt]);
            KT_STEP(Ca, 48, kt);
        }

        // ---- view: 59 -> 32 (tiles 64..95) ----
        float ex[4], ey[4], ez[4];
#pragma unroll
        for (int j = 0; j < 4; j++) {
            int src = 16 * (j >> 1) + 8 * (j & 1) + g;
            ex[j] = __shfl_sync(FULL, dvx, src);
            ey[j] = __shfl_sync(FULL, dvy, src);
            ez[j] = __shfl_sync(FULL, dvz, src);
        }
#pragma unroll
        for (int nt = 0; nt < 4; nt++) {
            float bb0 = sm[128 + nt * 8 + 2 * tc], bb1 = sm[128 + nt * 8 + 2 * tc + 1];
#pragma unroll
            for (int mt = 0; mt < 2; mt++) {
                Cb[mt][nt][0] = bb0; Cb[mt][nt][1] = bb1;
                Cb[mt][nt][2] = bb0; Cb[mt][nt][3] = bb1;
            }
        }
#pragma unroll
        for (int kt = 0; kt < 8; kt++) {
#pragma unroll
            for (int mt = 0; mt < 2; mt++) {
                if (kt < 4) {
                    build_afrag(Ca[mt][kt][0], Ca[mt][kt][1], Ca[mt][kt][2], Ca[mt][kt][3],
                                A1[mt], A2[mt]);
                } else {
                    int cd0 = 8 * (kt - 4) + 2 * tc, cd1 = cd0 + 1;
                    float v0 = embcol(ex[2 * mt], ey[2 * mt], ez[2 * mt], cd0, 27);
                    float v1 = embcol(ex[2 * mt], ey[2 * mt], ez[2 * mt], cd1, 27);
                    float v2 = embcol(ex[2 * mt + 1], ey[2 * mt + 1], ez[2 * mt + 1], cd0, 27);
                    float v3 = embcol(ex[2 * mt + 1], ey[2 * mt + 1], ez[2 * mt + 1], cd1, 27);
                    build_afrag(v0, v1, v2, v3, A1[mt], A2[mt]);
                }
            }
            KT_STEP(Cb, 64, kt);
        }
#pragma unroll
        for (int mt = 0; mt < 2; mt++)
#pragma unroll
            for (int nt = 0; nt < 4; nt++)
#pragma unroll
                for (int r = 0; r < 4; r++)
                    Cb[mt][nt][r] = fmaxf(Cb[mt][nt][r], 0.f);

        // ---- epilogue: rgb partials per row + butterfly over tc group ----
        float rr[4][3];
#pragma unroll
        for (int mt = 0; mt < 2; mt++)
#pragma unroll
            for (int h = 0; h < 2; h++) {
                float a0 = 0.f, a1 = 0.f, a2 = 0.f;
#pragma unroll
                for (int nt = 0; nt < 4; nt++) {
                    int col0 = nt * 8 + 2 * tc, col1 = col0 + 1;
                    float v0 = Cb[mt][nt][2 * h], v1 = Cb[mt][nt][2 * h + 1];
                    a0 += v0 * sm[160 + col0 * 3 + 0] + v1 * sm[160 + col1 * 3 + 0];
                    a1 += v0 * sm[160 + col0 * 3 + 1] + v1 * sm[160 + col1 * 3 + 1];
                    a2 += v0 * sm[160 + col0 * 3 + 2] + v1 * sm[160 + col1 * 3 + 2];
                }
                rr[2 * mt + h][0] = a0; rr[2 * mt + h][1] = a1; rr[2 * mt + h][2] = a2;
            }
#pragma unroll
        for (int j = 0; j < 4; j++) {
#pragma unroll
            for (int ch = 0; ch < 3; ch++) {
                rr[j][ch] += __shfl_xor_sync(FULL, rr[j][ch], 1);
                rr[j][ch] += __shfl_xor_sync(FULL, rr[j][ch], 2);
            }
            sg[j] += __shfl_xor_sync(FULL, sg[j], 1);
            sg[j] += __shfl_xor_sync(FULL, sg[j], 2);
        }

        // thread tc writes row j=tc: row = 16*(tc>>1) + 8*(tc&1) + g
        {
            int row = 16 * (tc >> 1) + 8 * (tc & 1) + g;
            int nn = __shfl_sync(FULL, n, row);
            if (base + row < count) {
                out[3 * nn + 0] = rr[tc][0] + sm[256];
                out[3 * nn + 1] = rr[tc][1] + sm[257];
                out[3 * nn + 2] = rr[tc][2] + sm[258];
                out[(size_t)NPTS * 3 + nn] = sg[tc] + sm[259];
            }
        }
    }
}

extern "C" void kernel_launch(void* const* d_in, const int* in_sizes, int n_in,
                              void* d_out, int out_size) {
    (void)in_sizes; (void)n_in; (void)out_size;
    const float* pts = (const float*)d_in[0];
    const float* vd  = (const float*)d_in[1];
    const float* w0  = (const float*)d_in[2];
    const float* b0  = (const float*)d_in[3];
    const float* w1  = (const float*)d_in[4];
    const float* b1  = (const float*)d_in[5];
    const float* fw  = (const float*)d_in[6];
    const float* fb  = (const float*)d_in[7];
    const float* sw  = (const float*)d_in[8];
    const float* sb  = (const float*)d_in[9];
    const float* vw  = (const float*)d_in[10];
    const float* vb  = (const float*)d_in[11];
    const float* rw  = (const float*)d_in[12];
    const float* rb  = (const float*)d_in[13];

    k_index<<<512, 256>>>(pts);
    k_scan<<<1, 1024>>>();
    k_scatter<<<512, 256>>>();
    k_mlp<<<NM, 64>>>(pts, vd, w0, b0, w1, b1, fw, fb, sw, sb, vw, vb, rw, rb,
                      (float*)d_out);
}